// round 1
// baseline (speedup 1.0000x reference)
#include <cuda_runtime.h>
#include <math.h>

#define NN 64
#define CC 64
#define TDIM 300
#define VV 25
#define OC 64
#define ROWS (NN*CC)          // 4096
#define PLANE (TDIM*VV)       // 7500
#define TOT (NN*CC*TDIM*VV)   // 30,720,000
#define CNT_F 480000.0f       // N*T*V per-channel BN count
#define TCH 10                // t's per thread in conv kernel

// ---------------- scratch (device globals: no allocs allowed) ----------------
__device__ float g_y[ROWS*TDIM];        // temporal diff, V-pooled
__device__ float g_s[ROWS*TDIM];        // sigmoid gate
__device__ float g_xg[TOT + 64];        // gated input (padded: lanes 25..31 over-read harmlessly)
__device__ float g_c1[TOT];             // conv outputs (pre-BN)
__device__ float g_c2[TOT];
__device__ float g_c3[TOT];
__device__ float g_sum[384];            // [0:192) sums, [192:384) sumsq  (conv-major, 64 oc each)
__device__ float g_scale[3*OC];
__device__ float g_shift[3*OC];

// ---------------- K1: p[t]=mean_v x; y[t]=p[t+1]-p[t], y[T-1]=0 ----------------
__global__ void k_pooldiff(const float* __restrict__ x) {
    int r = blockIdx.x;         // 0..4095
    int t = threadIdx.x;        // 0..299 (blockDim = 300)
    __shared__ float p[TDIM];
    const float* xp = x + (size_t)r * PLANE + t * VV;
    float s = 0.f;
    #pragma unroll
    for (int v = 0; v < VV; v++) s += xp[v];
    p[t] = s * (1.0f / VV);
    __syncthreads();
    g_y[r*TDIM + t] = (t < TDIM-1) ? (p[t+1] - p[t]) : 0.f;
}

// ---------------- K2: S = sigmoid(Y @ Wse^T), 16 rows per block ----------------
__global__ void k_gate(const float* __restrict__ wse) {
    const int R = 16;
    int r0 = blockIdx.x * R;
    int t  = threadIdx.x;       // 0..299 (blockDim = 300)
    __shared__ float ys[R][TDIM];
    for (int i = t; i < R*TDIM; i += TDIM)
        ys[i / TDIM][i % TDIM] = g_y[(r0 + i / TDIM)*TDIM + (i % TDIM)];
    __syncthreads();
    float acc[R];
    #pragma unroll
    for (int i = 0; i < R; i++) acc[i] = 0.f;
    const float* wrow = wse + t * TDIM;   // s[r,t] = sum_k y[r,k] * wse[t,k]
    for (int k = 0; k < TDIM; k++) {
        float w = wrow[k];
        #pragma unroll
        for (int i = 0; i < R; i++) acc[i] += ys[i][k] * w;
    }
    #pragma unroll
    for (int i = 0; i < R; i++)
        g_s[(r0 + i)*TDIM + t] = 1.f / (1.f + __expf(-acc[i]));
}

// ---------------- K3: xg = x * s (broadcast over V) ----------------
__global__ void k_xg(const float* __restrict__ x) {
    int idx = blockIdx.x * blockDim.x + threadIdx.x;
    if (idx >= TOT) return;
    g_xg[idx] = x[idx] * g_s[idx / VV];
}

// ---------------- K4: zero stats (graph replays must be deterministic) ----------------
__global__ void k_zero() {
    g_sum[threadIdx.x] = 0.f;
}

// ---------------- K5: 3 dilated convs + per-channel sum/sumsq ----------------
// Thread = (n, oc, v) computing TCH consecutive t's via a sliding register window.
__global__ void __launch_bounds__(256) k_conv(
    const float* __restrict__ w1, const float* __restrict__ b1,
    const float* __restrict__ w2, const float* __restrict__ b2,
    const float* __restrict__ w3, const float* __restrict__ b3)
{
    int n    = blockIdx.z;
    int wid  = threadIdx.x >> 5;
    int lane = threadIdx.x & 31;
    int oc   = blockIdx.y * 8 + wid;
    int t0   = blockIdx.x * TCH;
    int v    = lane;                       // active if < 25

    float acc1[TCH], acc2[TCH], acc3[TCH];
    #pragma unroll
    for (int i = 0; i < TCH; i++) { acc1[i]=0.f; acc2[i]=0.f; acc3[i]=0.f; }

    const float* xbase = g_xg + (size_t)n * CC * PLANE + v;
    const float* w1p = w1 + oc * CC * 3;
    const float* w2p = w2 + oc * CC * 3;
    const float* w3p = w3 + oc * CC * 3;

    for (int ic = 0; ic < CC; ic++) {
        const float* xr = xbase + (size_t)ic * PLANE;
        float xw[TCH + 6];
        #pragma unroll
        for (int u = 0; u < TCH + 6; u++) {
            int t = t0 - 3 + u;
            xw[u] = (t >= 0 && t < TDIM) ? xr[t * VV] : 0.f;
        }
        float a0 = w1p[ic*3+0], a1 = w1p[ic*3+1], a2 = w1p[ic*3+2];
        float c0 = w2p[ic*3+0], c1 = w2p[ic*3+1], c2 = w2p[ic*3+2];
        float e0 = w3p[ic*3+0], e1 = w3p[ic*3+1], e2 = w3p[ic*3+2];
        #pragma unroll
        for (int tt = 0; tt < TCH; tt++) {
            float x0 = xw[tt+3];
            acc1[tt] += a0*xw[tt+2] + a1*x0 + a2*xw[tt+4];   // dil 1: t-1, t, t+1
            acc2[tt] += c0*xw[tt+1] + c1*x0 + c2*xw[tt+5];   // dil 2: t-2, t, t+2
            acc3[tt] += e0*xw[tt+0] + e1*x0 + e2*xw[tt+6];   // dil 3: t-3, t, t+3
        }
    }

    float bb1 = b1[oc], bb2 = b2[oc], bb3 = b3[oc];
    float s1=0.f,s2=0.f,s3=0.f,q1=0.f,q2=0.f,q3=0.f;
    size_t obase = (((size_t)n * OC + oc) * TDIM + t0) * VV + v;
    bool act = (v < VV);
    #pragma unroll
    for (int tt = 0; tt < TCH; tt++) {
        float c1v = acc1[tt] + bb1;
        float c2v = acc2[tt] + bb2;
        float c3v = acc3[tt] + bb3;
        if (act) {
            g_c1[obase + (size_t)tt*VV] = c1v;
            g_c2[obase + (size_t)tt*VV] = c2v;
            g_c3[obase + (size_t)tt*VV] = c3v;
            s1 += c1v; q1 += c1v*c1v;
            s2 += c2v; q2 += c2v*c2v;
            s3 += c3v; q3 += c3v*c3v;
        }
    }
    // warp reduction (inactive lanes contribute 0)
    #pragma unroll
    for (int off = 16; off; off >>= 1) {
        s1 += __shfl_down_sync(0xffffffffu, s1, off);
        q1 += __shfl_down_sync(0xffffffffu, q1, off);
        s2 += __shfl_down_sync(0xffffffffu, s2, off);
        q2 += __shfl_down_sync(0xffffffffu, q2, off);
        s3 += __shfl_down_sync(0xffffffffu, s3, off);
        q3 += __shfl_down_sync(0xffffffffu, q3, off);
    }
    if (lane == 0) {
        atomicAdd(&g_sum[0*OC + oc],       s1);
        atomicAdd(&g_sum[192 + 0*OC + oc], q1);
        atomicAdd(&g_sum[1*OC + oc],       s2);
        atomicAdd(&g_sum[192 + 1*OC + oc], q2);
        atomicAdd(&g_sum[2*OC + oc],       s3);
        atomicAdd(&g_sum[192 + 2*OC + oc], q3);
    }
}

// ---------------- K6: finalize BN affine params ----------------
__global__ void k_bn(const float* __restrict__ g1, const float* __restrict__ be1,
                     const float* __restrict__ g2, const float* __restrict__ be2,
                     const float* __restrict__ g3, const float* __restrict__ be3)
{
    int i = threadIdx.x;            // 0..191
    int conv = i / OC, oc = i % OC;
    float mean = g_sum[i] * (1.0f / CNT_F);
    float var  = g_sum[192 + i] * (1.0f / CNT_F) - mean * mean;
    const float* g  = (conv == 0) ? g1  : (conv == 1) ? g2  : g3;
    const float* be = (conv == 0) ? be1 : (conv == 1) ? be2 : be3;
    float sc = g[oc] * rsqrtf(var + 1e-5f);
    g_scale[i] = sc;
    g_shift[i] = be[oc] - sc * mean;
}

// ---------------- K7: out = sum_i scale_i*c_i + shift_i ----------------
__global__ void k_out(float* __restrict__ out) {
    int i4 = blockIdx.x * blockDim.x + threadIdx.x;
    int idx = i4 * 4;
    if (idx >= TOT) return;
    int oc = (idx / PLANE) % OC;    // PLANE % 4 == 0: float4 never crosses a channel
    float sc1 = g_scale[oc], sc2 = g_scale[64 + oc], sc3 = g_scale[128 + oc];
    float sh  = g_shift[oc] + g_shift[64 + oc] + g_shift[128 + oc];
    float4 a = *(const float4*)(g_c1 + idx);
    float4 b = *(const float4*)(g_c2 + idx);
    float4 c = *(const float4*)(g_c3 + idx);
    float4 o;
    o.x = sc1*a.x + sc2*b.x + sc3*c.x + sh;
    o.y = sc1*a.y + sc2*b.y + sc3*c.y + sh;
    o.z = sc1*a.z + sc2*b.z + sc3*c.z + sh;
    o.w = sc1*a.w + sc2*b.w + sc3*c.w + sh;
    *(float4*)(out + idx) = o;
}

// ---------------- launch ----------------
extern "C" void kernel_launch(void* const* d_in, const int* in_sizes, int n_in,
                              void* d_out, int out_size) {
    const float* x   = (const float*)d_in[0];
    const float* wse = (const float*)d_in[1];
    const float* w1  = (const float*)d_in[2];
    const float* b1  = (const float*)d_in[3];
    const float* w2  = (const float*)d_in[4];
    const float* b2  = (const float*)d_in[5];
    const float* w3  = (const float*)d_in[6];
    const float* b3  = (const float*)d_in[7];
    const float* g1  = (const float*)d_in[8];
    const float* be1 = (const float*)d_in[9];
    const float* g2  = (const float*)d_in[10];
    const float* be2 = (const float*)d_in[11];
    const float* g3  = (const float*)d_in[12];
    const float* be3 = (const float*)d_in[13];
    float* out = (float*)d_out;

    k_pooldiff<<<ROWS, TDIM>>>(x);
    k_gate<<<ROWS/16, TDIM>>>(wse);
    k_xg<<<(TOT + 255)/256, 256>>>(x);
    k_zero<<<1, 384>>>();
    k_conv<<<dim3(TDIM/TCH, OC/8, NN), 256>>>(w1, b1, w2, b2, w3, b3);
    k_bn<<<1, 192>>>(g1, be1, g2, be2, g3, be3);
    k_out<<<(TOT/4 + 255)/256, 256>>>(out);
}

// round 2
// speedup vs baseline: 1.0007x; 1.0007x over previous
#include <cuda_runtime.h>
#include <math.h>

#define NN 64
#define CC 64
#define TDIM 300
#define VV 25
#define OC 64
#define ROWS (NN*CC)          // 4096
#define PLANE (TDIM*VV)       // 7500
#define TOT (NN*CC*TDIM*VV)   // 30,720,000
#define CNT_F 480000.0f       // N*T*V per-channel BN count
#define TCH 10                // t's per thread in conv kernel

// ---------------- scratch (device globals: no allocs allowed) ----------------
__device__ float g_y[ROWS*TDIM];        // temporal diff, V-pooled
__device__ float g_s[ROWS*TDIM];        // sigmoid gate
__device__ float g_xg[TOT + 64];        // gated input (padded: lanes 25..31 over-read harmlessly)
__device__ float g_c1[TOT];             // conv outputs (pre-BN)
__device__ float g_c2[TOT];
__device__ float g_c3[TOT];
__device__ float g_sum[384];            // [0:192) sums, [192:384) sumsq  (conv-major, 64 oc each)
__device__ float g_scale[3*OC];
__device__ float g_shift[3*OC];

// ---------------- K1: p[t]=mean_v x; y[t]=p[t+1]-p[t], y[T-1]=0 ----------------
__global__ void k_pooldiff(const float* __restrict__ x) {
    int r = blockIdx.x;         // 0..4095
    int t = threadIdx.x;        // 0..299 (blockDim = 300)
    __shared__ float p[TDIM];
    const float* xp = x + (size_t)r * PLANE + t * VV;
    float s = 0.f;
    #pragma unroll
    for (int v = 0; v < VV; v++) s += xp[v];
    p[t] = s * (1.0f / VV);
    __syncthreads();
    g_y[r*TDIM + t] = (t < TDIM-1) ? (p[t+1] - p[t]) : 0.f;
}

// ---------------- K2: S = sigmoid(Y @ Wse^T), 16 rows per block ----------------
__global__ void k_gate(const float* __restrict__ wse) {
    const int R = 16;
    int r0 = blockIdx.x * R;
    int t  = threadIdx.x;       // 0..299 (blockDim = 300)
    __shared__ float ys[R][TDIM];
    for (int i = t; i < R*TDIM; i += TDIM)
        ys[i / TDIM][i % TDIM] = g_y[(r0 + i / TDIM)*TDIM + (i % TDIM)];
    __syncthreads();
    float acc[R];
    #pragma unroll
    for (int i = 0; i < R; i++) acc[i] = 0.f;
    const float* wrow = wse + t * TDIM;   // s[r,t] = sum_k y[r,k] * wse[t,k]
    for (int k = 0; k < TDIM; k++) {
        float w = wrow[k];
        #pragma unroll
        for (int i = 0; i < R; i++) acc[i] += ys[i][k] * w;
    }
    #pragma unroll
    for (int i = 0; i < R; i++)
        g_s[(r0 + i)*TDIM + t] = 1.f / (1.f + __expf(-acc[i]));
}

// ---------------- K3: xg = x * s (broadcast over V) ----------------
__global__ void k_xg(const float* __restrict__ x) {
    int idx = blockIdx.x * blockDim.x + threadIdx.x;
    if (idx >= TOT) return;
    g_xg[idx] = x[idx] * g_s[idx / VV];
}

// ---------------- K4: zero stats (graph replays must be deterministic) ----------------
__global__ void k_zero() {
    g_sum[threadIdx.x] = 0.f;
}

// ---------------- K5: 3 dilated convs + per-channel sum/sumsq ----------------
// Thread = (n, oc, v) computing TCH consecutive t's via a sliding register window.
__global__ void __launch_bounds__(256) k_conv(
    const float* __restrict__ w1, const float* __restrict__ b1,
    const float* __restrict__ w2, const float* __restrict__ b2,
    const float* __restrict__ w3, const float* __restrict__ b3)
{
    int n    = blockIdx.z;
    int wid  = threadIdx.x >> 5;
    int lane = threadIdx.x & 31;
    int oc   = blockIdx.y * 8 + wid;
    int t0   = blockIdx.x * TCH;
    int v    = lane;                       // active if < 25

    float acc1[TCH], acc2[TCH], acc3[TCH];
    #pragma unroll
    for (int i = 0; i < TCH; i++) { acc1[i]=0.f; acc2[i]=0.f; acc3[i]=0.f; }

    const float* xbase = g_xg + (size_t)n * CC * PLANE + v;
    const float* w1p = w1 + oc * CC * 3;
    const float* w2p = w2 + oc * CC * 3;
    const float* w3p = w3 + oc * CC * 3;

    for (int ic = 0; ic < CC; ic++) {
        const float* xr = xbase + (size_t)ic * PLANE;
        float xw[TCH + 6];
        #pragma unroll
        for (int u = 0; u < TCH + 6; u++) {
            int t = t0 - 3 + u;
            xw[u] = (t >= 0 && t < TDIM) ? xr[t * VV] : 0.f;
        }
        float a0 = w1p[ic*3+0], a1 = w1p[ic*3+1], a2 = w1p[ic*3+2];
        float c0 = w2p[ic*3+0], c1 = w2p[ic*3+1], c2 = w2p[ic*3+2];
        float e0 = w3p[ic*3+0], e1 = w3p[ic*3+1], e2 = w3p[ic*3+2];
        #pragma unroll
        for (int tt = 0; tt < TCH; tt++) {
            float x0 = xw[tt+3];
            acc1[tt] += a0*xw[tt+2] + a1*x0 + a2*xw[tt+4];   // dil 1: t-1, t, t+1
            acc2[tt] += c0*xw[tt+1] + c1*x0 + c2*xw[tt+5];   // dil 2: t-2, t, t+2
            acc3[tt] += e0*xw[tt+0] + e1*x0 + e2*xw[tt+6];   // dil 3: t-3, t, t+3
        }
    }

    float bb1 = b1[oc], bb2 = b2[oc], bb3 = b3[oc];
    float s1=0.f,s2=0.f,s3=0.f,q1=0.f,q2=0.f,q3=0.f;
    size_t obase = (((size_t)n * OC + oc) * TDIM + t0) * VV + v;
    bool act = (v < VV);
    #pragma unroll
    for (int tt = 0; tt < TCH; tt++) {
        float c1v = acc1[tt] + bb1;
        float c2v = acc2[tt] + bb2;
        float c3v = acc3[tt] + bb3;
        if (act) {
            g_c1[obase + (size_t)tt*VV] = c1v;
            g_c2[obase + (size_t)tt*VV] = c2v;
            g_c3[obase + (size_t)tt*VV] = c3v;
            s1 += c1v; q1 += c1v*c1v;
            s2 += c2v; q2 += c2v*c2v;
            s3 += c3v; q3 += c3v*c3v;
        }
    }
    // warp reduction (inactive lanes contribute 0)
    #pragma unroll
    for (int off = 16; off; off >>= 1) {
        s1 += __shfl_down_sync(0xffffffffu, s1, off);
        q1 += __shfl_down_sync(0xffffffffu, q1, off);
        s2 += __shfl_down_sync(0xffffffffu, s2, off);
        q2 += __shfl_down_sync(0xffffffffu, q2, off);
        s3 += __shfl_down_sync(0xffffffffu, s3, off);
        q3 += __shfl_down_sync(0xffffffffu, q3, off);
    }
    if (lane == 0) {
        atomicAdd(&g_sum[0*OC + oc],       s1);
        atomicAdd(&g_sum[192 + 0*OC + oc], q1);
        atomicAdd(&g_sum[1*OC + oc],       s2);
        atomicAdd(&g_sum[192 + 1*OC + oc], q2);
        atomicAdd(&g_sum[2*OC + oc],       s3);
        atomicAdd(&g_sum[192 + 2*OC + oc], q3);
    }
}

// ---------------- K6: finalize BN affine params ----------------
__global__ void k_bn(const float* __restrict__ g1, const float* __restrict__ be1,
                     const float* __restrict__ g2, const float* __restrict__ be2,
                     const float* __restrict__ g3, const float* __restrict__ be3)
{
    int i = threadIdx.x;            // 0..191
    int conv = i / OC, oc = i % OC;
    float mean = g_sum[i] * (1.0f / CNT_F);
    float var  = g_sum[192 + i] * (1.0f / CNT_F) - mean * mean;
    const float* g  = (conv == 0) ? g1  : (conv == 1) ? g2  : g3;
    const float* be = (conv == 0) ? be1 : (conv == 1) ? be2 : be3;
    float sc = g[oc] * rsqrtf(var + 1e-5f);
    g_scale[i] = sc;
    g_shift[i] = be[oc] - sc * mean;
}

// ---------------- K7: out = sum_i scale_i*c_i + shift_i ----------------
__global__ void k_out(float* __restrict__ out) {
    int i4 = blockIdx.x * blockDim.x + threadIdx.x;
    int idx = i4 * 4;
    if (idx >= TOT) return;
    int oc = (idx / PLANE) % OC;    // PLANE % 4 == 0: float4 never crosses a channel
    float sc1 = g_scale[oc], sc2 = g_scale[64 + oc], sc3 = g_scale[128 + oc];
    float sh  = g_shift[oc] + g_shift[64 + oc] + g_shift[128 + oc];
    float4 a = *(const float4*)(g_c1 + idx);
    float4 b = *(const float4*)(g_c2 + idx);
    float4 c = *(const float4*)(g_c3 + idx);
    float4 o;
    o.x = sc1*a.x + sc2*b.x + sc3*c.x + sh;
    o.y = sc1*a.y + sc2*b.y + sc3*c.y + sh;
    o.z = sc1*a.z + sc2*b.z + sc3*c.z + sh;
    o.w = sc1*a.w + sc2*b.w + sc3*c.w + sh;
    *(float4*)(out + idx) = o;
}

// ---------------- launch ----------------
extern "C" void kernel_launch(void* const* d_in, const int* in_sizes, int n_in,
                              void* d_out, int out_size) {
    const float* x   = (const float*)d_in[0];
    const float* wse = (const float*)d_in[1];
    const float* w1  = (const float*)d_in[2];
    const float* b1  = (const float*)d_in[3];
    const float* w2  = (const float*)d_in[4];
    const float* b2  = (const float*)d_in[5];
    const float* w3  = (const float*)d_in[6];
    const float* b3  = (const float*)d_in[7];
    const float* g1  = (const float*)d_in[8];
    const float* be1 = (const float*)d_in[9];
    const float* g2  = (const float*)d_in[10];
    const float* be2 = (const float*)d_in[11];
    const float* g3  = (const float*)d_in[12];
    const float* be3 = (const float*)d_in[13];
    float* out = (float*)d_out;

    k_pooldiff<<<ROWS, TDIM>>>(x);
    k_gate<<<ROWS/16, TDIM>>>(wse);
    k_xg<<<(TOT + 255)/256, 256>>>(x);
    k_zero<<<1, 384>>>();
    k_conv<<<dim3(TDIM/TCH, OC/8, NN), 256>>>(w1, b1, w2, b2, w3, b3);
    k_bn<<<1, 192>>>(g1, be1, g2, be2, g3, be3);
    k_out<<<(TOT/4 + 255)/256, 256>>>(out);
}

// round 3
// speedup vs baseline: 1.0009x; 1.0002x over previous
#include <cuda_runtime.h>
#include <math.h>

#define NN 64
#define CC 64
#define TDIM 300
#define VV 25
#define OC 64
#define ROWS (NN*CC)          // 4096
#define PLANE (TDIM*VV)       // 7500
#define TOT (NN*CC*TDIM*VV)   // 30,720,000
#define CNT_F 480000.0f       // N*T*V per-channel BN count
#define TCH 10                // t's per thread in conv kernel

// ---------------- scratch (device globals: no allocs allowed) ----------------
__device__ float g_y[ROWS*TDIM];        // temporal diff, V-pooled
__device__ float g_s[ROWS*TDIM];        // sigmoid gate
__device__ float g_xg[TOT + 64];        // gated input (padded: lanes 25..31 over-read harmlessly)
__device__ float g_c1[TOT];             // conv outputs (pre-BN)
__device__ float g_c2[TOT];
__device__ float g_c3[TOT];
__device__ float g_sum[384];            // [0:192) sums, [192:384) sumsq  (conv-major, 64 oc each)
__device__ float g_scale[3*OC];
__device__ float g_shift[3*OC];

// ---------------- K1: p[t]=mean_v x; y[t]=p[t+1]-p[t], y[T-1]=0 ----------------
__global__ void k_pooldiff(const float* __restrict__ x) {
    int r = blockIdx.x;         // 0..4095
    int t = threadIdx.x;        // 0..299 (blockDim = 300)
    __shared__ float p[TDIM];
    const float* xp = x + (size_t)r * PLANE + t * VV;
    float s = 0.f;
    #pragma unroll
    for (int v = 0; v < VV; v++) s += xp[v];
    p[t] = s * (1.0f / VV);
    __syncthreads();
    g_y[r*TDIM + t] = (t < TDIM-1) ? (p[t+1] - p[t]) : 0.f;
}

// ---------------- K2: S = sigmoid(Y @ Wse^T), 16 rows per block ----------------
__global__ void k_gate(const float* __restrict__ wse) {
    const int R = 16;
    int r0 = blockIdx.x * R;
    int t  = threadIdx.x;       // 0..299 (blockDim = 300)
    __shared__ float ys[R][TDIM];
    for (int i = t; i < R*TDIM; i += TDIM)
        ys[i / TDIM][i % TDIM] = g_y[(r0 + i / TDIM)*TDIM + (i % TDIM)];
    __syncthreads();
    float acc[R];
    #pragma unroll
    for (int i = 0; i < R; i++) acc[i] = 0.f;
    const float* wrow = wse + t * TDIM;   // s[r,t] = sum_k y[r,k] * wse[t,k]
    for (int k = 0; k < TDIM; k++) {
        float w = wrow[k];
        #pragma unroll
        for (int i = 0; i < R; i++) acc[i] += ys[i][k] * w;
    }
    #pragma unroll
    for (int i = 0; i < R; i++)
        g_s[(r0 + i)*TDIM + t] = 1.f / (1.f + __expf(-acc[i]));
}

// ---------------- K3: xg = x * s (broadcast over V) ----------------
__global__ void k_xg(const float* __restrict__ x) {
    int idx = blockIdx.x * blockDim.x + threadIdx.x;
    if (idx >= TOT) return;
    g_xg[idx] = x[idx] * g_s[idx / VV];
}

// ---------------- K4: zero stats (graph replays must be deterministic) ----------------
__global__ void k_zero() {
    g_sum[threadIdx.x] = 0.f;
}

// ---------------- K5: 3 dilated convs + per-channel sum/sumsq ----------------
// Thread = (n, oc, v) computing TCH consecutive t's via a sliding register window.
__global__ void __launch_bounds__(256) k_conv(
    const float* __restrict__ w1, const float* __restrict__ b1,
    const float* __restrict__ w2, const float* __restrict__ b2,
    const float* __restrict__ w3, const float* __restrict__ b3)
{
    int n    = blockIdx.z;
    int wid  = threadIdx.x >> 5;
    int lane = threadIdx.x & 31;
    int oc   = blockIdx.y * 8 + wid;
    int t0   = blockIdx.x * TCH;
    int v    = lane;                       // active if < 25

    float acc1[TCH], acc2[TCH], acc3[TCH];
    #pragma unroll
    for (int i = 0; i < TCH; i++) { acc1[i]=0.f; acc2[i]=0.f; acc3[i]=0.f; }

    const float* xbase = g_xg + (size_t)n * CC * PLANE + v;
    const float* w1p = w1 + oc * CC * 3;
    const float* w2p = w2 + oc * CC * 3;
    const float* w3p = w3 + oc * CC * 3;

    for (int ic = 0; ic < CC; ic++) {
        const float* xr = xbase + (size_t)ic * PLANE;
        float xw[TCH + 6];
        #pragma unroll
        for (int u = 0; u < TCH + 6; u++) {
            int t = t0 - 3 + u;
            xw[u] = (t >= 0 && t < TDIM) ? xr[t * VV] : 0.f;
        }
        float a0 = w1p[ic*3+0], a1 = w1p[ic*3+1], a2 = w1p[ic*3+2];
        float c0 = w2p[ic*3+0], c1 = w2p[ic*3+1], c2 = w2p[ic*3+2];
        float e0 = w3p[ic*3+0], e1 = w3p[ic*3+1], e2 = w3p[ic*3+2];
        #pragma unroll
        for (int tt = 0; tt < TCH; tt++) {
            float x0 = xw[tt+3];
            acc1[tt] += a0*xw[tt+2] + a1*x0 + a2*xw[tt+4];   // dil 1: t-1, t, t+1
            acc2[tt] += c0*xw[tt+1] + c1*x0 + c2*xw[tt+5];   // dil 2: t-2, t, t+2
            acc3[tt] += e0*xw[tt+0] + e1*x0 + e2*xw[tt+6];   // dil 3: t-3, t, t+3
        }
    }

    float bb1 = b1[oc], bb2 = b2[oc], bb3 = b3[oc];
    float s1=0.f,s2=0.f,s3=0.f,q1=0.f,q2=0.f,q3=0.f;
    size_t obase = (((size_t)n * OC + oc) * TDIM + t0) * VV + v;
    bool act = (v < VV);
    #pragma unroll
    for (int tt = 0; tt < TCH; tt++) {
        float c1v = acc1[tt] + bb1;
        float c2v = acc2[tt] + bb2;
        float c3v = acc3[tt] + bb3;
        if (act) {
            g_c1[obase + (size_t)tt*VV] = c1v;
            g_c2[obase + (size_t)tt*VV] = c2v;
            g_c3[obase + (size_t)tt*VV] = c3v;
            s1 += c1v; q1 += c1v*c1v;
            s2 += c2v; q2 += c2v*c2v;
            s3 += c3v; q3 += c3v*c3v;
        }
    }
    // warp reduction (inactive lanes contribute 0)
    #pragma unroll
    for (int off = 16; off; off >>= 1) {
        s1 += __shfl_down_sync(0xffffffffu, s1, off);
        q1 += __shfl_down_sync(0xffffffffu, q1, off);
        s2 += __shfl_down_sync(0xffffffffu, s2, off);
        q2 += __shfl_down_sync(0xffffffffu, q2, off);
        s3 += __shfl_down_sync(0xffffffffu, s3, off);
        q3 += __shfl_down_sync(0xffffffffu, q3, off);
    }
    if (lane == 0) {
        atomicAdd(&g_sum[0*OC + oc],       s1);
        atomicAdd(&g_sum[192 + 0*OC + oc], q1);
        atomicAdd(&g_sum[1*OC + oc],       s2);
        atomicAdd(&g_sum[192 + 1*OC + oc], q2);
        atomicAdd(&g_sum[2*OC + oc],       s3);
        atomicAdd(&g_sum[192 + 2*OC + oc], q3);
    }
}

// ---------------- K6: finalize BN affine params ----------------
__global__ void k_bn(const float* __restrict__ g1, const float* __restrict__ be1,
                     const float* __restrict__ g2, const float* __restrict__ be2,
                     const float* __restrict__ g3, const float* __restrict__ be3)
{
    int i = threadIdx.x;            // 0..191
    int conv = i / OC, oc = i % OC;
    float mean = g_sum[i] * (1.0f / CNT_F);
    float var  = g_sum[192 + i] * (1.0f / CNT_F) - mean * mean;
    const float* g  = (conv == 0) ? g1  : (conv == 1) ? g2  : g3;
    const float* be = (conv == 0) ? be1 : (conv == 1) ? be2 : be3;
    float sc = g[oc] * rsqrtf(var + 1e-5f);
    g_scale[i] = sc;
    g_shift[i] = be[oc] - sc * mean;
}

// ---------------- K7: out = sum_i scale_i*c_i + shift_i ----------------
__global__ void k_out(float* __restrict__ out) {
    int i4 = blockIdx.x * blockDim.x + threadIdx.x;
    int idx = i4 * 4;
    if (idx >= TOT) return;
    int oc = (idx / PLANE) % OC;    // PLANE % 4 == 0: float4 never crosses a channel
    float sc1 = g_scale[oc], sc2 = g_scale[64 + oc], sc3 = g_scale[128 + oc];
    float sh  = g_shift[oc] + g_shift[64 + oc] + g_shift[128 + oc];
    float4 a = *(const float4*)(g_c1 + idx);
    float4 b = *(const float4*)(g_c2 + idx);
    float4 c = *(const float4*)(g_c3 + idx);
    float4 o;
    o.x = sc1*a.x + sc2*b.x + sc3*c.x + sh;
    o.y = sc1*a.y + sc2*b.y + sc3*c.y + sh;
    o.z = sc1*a.z + sc2*b.z + sc3*c.z + sh;
    o.w = sc1*a.w + sc2*b.w + sc3*c.w + sh;
    *(float4*)(out + idx) = o;
}

// ---------------- launch ----------------
extern "C" void kernel_launch(void* const* d_in, const int* in_sizes, int n_in,
                              void* d_out, int out_size) {
    const float* x   = (const float*)d_in[0];
    const float* wse = (const float*)d_in[1];
    const float* w1  = (const float*)d_in[2];
    const float* b1  = (const float*)d_in[3];
    const float* w2  = (const float*)d_in[4];
    const float* b2  = (const float*)d_in[5];
    const float* w3  = (const float*)d_in[6];
    const float* b3  = (const float*)d_in[7];
    const float* g1  = (const float*)d_in[8];
    const float* be1 = (const float*)d_in[9];
    const float* g2  = (const float*)d_in[10];
    const float* be2 = (const float*)d_in[11];
    const float* g3  = (const float*)d_in[12];
    const float* be3 = (const float*)d_in[13];
    float* out = (float*)d_out;

    k_pooldiff<<<ROWS, TDIM>>>(x);
    k_gate<<<ROWS/16, TDIM>>>(wse);
    k_xg<<<(TOT + 255)/256, 256>>>(x);
    k_zero<<<1, 384>>>();
    k_conv<<<dim3(TDIM/TCH, OC/8, NN), 256>>>(w1, b1, w2, b2, w3, b3);
    k_bn<<<1, 192>>>(g1, be1, g2, be2, g3, be3);
    k_out<<<(TOT/4 + 255)/256, 256>>>(out);
}